// round 13
// baseline (speedup 1.0000x reference)
#include <cuda_runtime.h>
#include <cstdint>

// Row-wise top-k(=6) thresholded renormalization.
//   delta = (6th largest of row) + 1e-7
//   w     = max(v - delta, 0) ;  out = w / (sum(w) + 1e-7)
//
// R13: each warp owns TWO rows. Row 0 loads via 8 front-batched LDG.128
// (register path, proven). Row 1 simultaneously streams into a shared
// stage via cp.async.cg (zero data registers), covering the warp's
// memory-silent selection/epilogue window. Candidate buffer is 64 entries
// with an exact lane-0 global-rescan fallback on overflow (never fires on
// real data; correctness holds for ANY input).
//   t    = 6th largest DISTINCT thread-max (ballot-free; provably <= v6)
//   cand = elements >= t ; v6 = 6th largest of cand (insertion, exact)

#define COLS    1024
#define TOPK    6
#define EPSV    1e-7f
#define WPB     4            // warps per block; each warp owns 2 rows
#define RPB     (WPB * 2)
#define CAND_CAP 64          // per-warp candidate slots (exact fallback on overflow)

__device__ __forceinline__ unsigned redux_max_u32(unsigned v) {
    unsigned r;
    asm volatile("redux.sync.max.u32 %0, %1, %2;"
                 : "=r"(r) : "r"(v), "r"(0xffffffffu));
    return r;
}
// monotone bijection: float ordering -> u32 ordering (exact, invertible)
__device__ __forceinline__ unsigned fkey(float f) {
    unsigned b = __float_as_uint(f);
    return b ^ ((unsigned)((int)b >> 31) | 0x80000000u);
}
__device__ __forceinline__ float funkey(unsigned k) {
    unsigned b = (k & 0x80000000u) ? (k ^ 0x80000000u) : ~k;
    return __uint_as_float(b);
}
__device__ __forceinline__ float4 fmax4(float4 a, float4 b) {
    return make_float4(fmaxf(a.x,b.x), fmaxf(a.y,b.y),
                       fmaxf(a.z,b.z), fmaxf(a.w,b.w));
}
__device__ __forceinline__ void cp_async16(void* smem_dst, const void* gmem_src) {
    unsigned s = (unsigned)__cvta_generic_to_shared(smem_dst);
    asm volatile("cp.async.cg.shared.global [%0], [%1], 16;"
                 :: "r"(s), "l"(gmem_src) : "memory");
}

// top-6 insertion step (descending s0..s5)
#define INS6(x) do { unsigned _x = (x); \
    if (_x > s5) { \
        if      (_x > s0) { s5=s4;s4=s3;s3=s2;s2=s1;s1=s0;s0=_x; } \
        else if (_x > s1) { s5=s4;s4=s3;s3=s2;s2=s1;s1=_x; } \
        else if (_x > s2) { s5=s4;s4=s3;s3=s2;s2=_x; } \
        else if (_x > s3) { s5=s4;s4=s3;s3=_x; } \
        else if (_x > s4) { s5=s4;s4=_x; } \
        else              { s5=_x; } } } while (0)

// Exact per-row selection + normalize + store. v[] is the row payload;
// rowin is the row's global base (used only by the overflow fallback).
__device__ __forceinline__ void process_row(
    float4 (&v)[8], const float* __restrict__ rowin, float* __restrict__ outrow,
    unsigned* __restrict__ cand, int* __restrict__ cnt, int lane)
{
    // per-thread max (31 FMNMX tree)
    float4 m01 = fmax4(v[0], v[1]), m23 = fmax4(v[2], v[3]);
    float4 m45 = fmax4(v[4], v[5]), m67 = fmax4(v[6], v[7]);
    float4 mm  = fmax4(fmax4(m01, m23), fmax4(m45, m67));
    float lmax = fmaxf(fmaxf(mm.x, mm.y), fmaxf(mm.z, mm.w));

    // t = 6th largest DISTINCT thread-max (ballot-free; t <= v6)
    unsigned a = fkey(lmax);
    unsigned kth = 0u;
#pragma unroll
    for (int r = 0; r < TOPK; ++r) {
        unsigned m = redux_max_u32(a);
        kth = m;
        if (a == m) a = 0u;
    }
    const float t = funkey(kth);

    // compact candidates (v >= t) into cand[0..CAND_CAP)
    if (lane == 0) *cnt = 0;
    __syncwarp();
    if (lmax >= t) {
#pragma unroll
        for (int i = 0; i < 8; ++i) {
            if (v[i].x >= t) { int ix = atomicAdd(cnt,1); if (ix < CAND_CAP) cand[ix] = fkey(v[i].x); }
            if (v[i].y >= t) { int ix = atomicAdd(cnt,1); if (ix < CAND_CAP) cand[ix] = fkey(v[i].y); }
            if (v[i].z >= t) { int ix = atomicAdd(cnt,1); if (ix < CAND_CAP) cand[ix] = fkey(v[i].z); }
            if (v[i].w >= t) { int ix = atomicAdd(cnt,1); if (ix < CAND_CAP) cand[ix] = fkey(v[i].w); }
        }
    }
    __syncwarp();

    // lane-0 insertion top-6 (exact); overflow -> exact full-row rescan
    float delta;
    if (lane == 0) {
        const int n = *cnt;
        unsigned s0=0u,s1=0u,s2=0u,s3=0u,s4=0u,s5=0u;
        if (n <= CAND_CAP) {
            for (int i = 0; i < n; ++i) INS6(cand[i]);
        } else {
            for (int i = 0; i < COLS; ++i) INS6(fkey(__ldg(rowin + i)));
        }
        delta = funkey(s5) + EPSV;
    }
    delta = __shfl_sync(0xffffffffu, delta, 0);

    // clamp in place, warp sum, normalize, store
    float4 acc = make_float4(0.f, 0.f, 0.f, 0.f);
#pragma unroll
    for (int i = 0; i < 8; ++i) {
        v[i].x = fmaxf(v[i].x - delta, 0.0f);
        v[i].y = fmaxf(v[i].y - delta, 0.0f);
        v[i].z = fmaxf(v[i].z - delta, 0.0f);
        v[i].w = fmaxf(v[i].w - delta, 0.0f);
        acc.x += v[i].x; acc.y += v[i].y; acc.z += v[i].z; acc.w += v[i].w;
    }
    float s = (acc.x + acc.y) + (acc.z + acc.w);
#pragma unroll
    for (int o = 16; o > 0; o >>= 1)
        s += __shfl_xor_sync(0xffffffffu, s, o);
    const float rinv = 1.0f / (s + EPSV);

    float4* op = reinterpret_cast<float4*>(outrow);
#pragma unroll
    for (int i = 0; i < 8; ++i) {
        float4 o4;
        o4.x = v[i].x * rinv; o4.y = v[i].y * rinv;
        o4.z = v[i].z * rinv; o4.w = v[i].w * rinv;
        __stcs(op + lane + 32 * i, o4);
    }
}

__global__ __launch_bounds__(32 * WPB)
void topk_renorm_kernel(const float* __restrict__ in,
                        float* __restrict__ out, int rows) {
    const int lane = threadIdx.x & 31;
    const int warp = threadIdx.x >> 5;
    const int row0 = (blockIdx.x * WPB + warp) * 2;
    const int row1 = row0 + 1;
    if (row0 >= rows) return;

    __shared__ float4   sh_stage[WPB][COLS / 4];   // row-1 staging (cp.async)
    __shared__ unsigned sh_cand[WPB][CAND_CAP];
    __shared__ int      sh_cnt[WPB];

    const float* rin0 = in + (size_t)row0 * COLS;
    const float* rin1 = in + (size_t)row1 * COLS;
    const bool has1 = (row1 < rows);

    // ---- row 0: 8 front-batched LDG.128 (register path) ----
    const float4* rp0 = reinterpret_cast<const float4*>(rin0);
    float4 v[8];
#pragma unroll
    for (int i = 0; i < 8; ++i) v[i] = __ldcs(rp0 + lane + 32 * i);

    // ---- row 1: stream into shared via cp.async (no data registers) ----
    if (has1) {
        const float4* rp1 = reinterpret_cast<const float4*>(rin1);
#pragma unroll
        for (int i = 0; i < 8; ++i)
            cp_async16(&sh_stage[warp][lane + 32 * i], rp1 + lane + 32 * i);
        asm volatile("cp.async.commit_group;" ::: "memory");
    }

    // ---- process row 0 while row 1 streams ----
    process_row(v, rin0, out + (size_t)row0 * COLS,
                sh_cand[warp], &sh_cnt[warp], lane);

    // ---- row 1: pull from shared (each thread reads its own copies) ----
    if (has1) {
        asm volatile("cp.async.wait_group 0;" ::: "memory");
#pragma unroll
        for (int i = 0; i < 8; ++i) v[i] = sh_stage[warp][lane + 32 * i];
        process_row(v, rin1, out + (size_t)row1 * COLS,
                    sh_cand[warp], &sh_cnt[warp], lane);
    }
}

extern "C" void kernel_launch(void* const* d_in, const int* in_sizes, int n_in,
                              void* d_out, int out_size) {
    const float* in = (const float*)d_in[0];
    float* out = (float*)d_out;
    const int rows = in_sizes[0] / COLS;           // 65536 for reference shape
    const int grid = (rows + RPB - 1) / RPB;
    topk_renorm_kernel<<<grid, 32 * WPB>>>(in, out, rows);
}

// round 14
// speedup vs baseline: 1.0293x; 1.0293x over previous
#include <cuda_runtime.h>
#include <cstdint>

// Row-wise top-k(=6) thresholded renormalization.
//   delta = (6th largest of row) + 1e-7
//   w     = max(v - delta, 0) ;  out = w / (sum(w) + 1e-7)
//
// R14 = R10 base (champion) + analytic sum:
//   Every element <= v6 clamps to exactly 0 (delta = v6+eps), and every
//   element > v6 is in the top-5 that lane 0 already holds (s0..s4). So
//   sum(w) = sum_{i<5} max(s_i - delta, 0)  — exact (fp32 +0 is identity).
//   This deletes the per-thread accumulate and the warp shuffle reduction;
//   lane 0 computes rinv directly and broadcasts {delta, rinv}.
//   t    = 6th largest DISTINCT thread-max (ballot-free; provably <= v6)
//   cand = all elements >= t (full-row shared buffer => exact for ANY input)
//   v6   = 6th largest of cand (lane-0 insertion top-6, exact multiset)

#define COLS   1024
#define TOPK   6
#define EPSV   1e-7f
#define WPB    4            // warps (=rows) per block

__device__ __forceinline__ unsigned redux_max_u32(unsigned v) {
    unsigned r;
    asm volatile("redux.sync.max.u32 %0, %1, %2;"
                 : "=r"(r) : "r"(v), "r"(0xffffffffu));
    return r;
}
// monotone bijection: float ordering -> u32 ordering (exact, invertible)
__device__ __forceinline__ unsigned fkey(float f) {
    unsigned b = __float_as_uint(f);
    return b ^ ((unsigned)((int)b >> 31) | 0x80000000u);
}
__device__ __forceinline__ float funkey(unsigned k) {
    unsigned b = (k & 0x80000000u) ? (k ^ 0x80000000u) : ~k;
    return __uint_as_float(b);
}
__device__ __forceinline__ float4 fmax4(float4 a, float4 b) {
    return make_float4(fmaxf(a.x,b.x), fmaxf(a.y,b.y),
                       fmaxf(a.z,b.z), fmaxf(a.w,b.w));
}

__global__ __launch_bounds__(32 * WPB)
void topk_renorm_kernel(const float* __restrict__ in,
                        float* __restrict__ out, int rows) {
    const int lane = threadIdx.x & 31;
    const int warp = threadIdx.x >> 5;
    const int row  = blockIdx.x * WPB + warp;
    if (row >= rows) return;

    __shared__ unsigned sh_cand[WPB][COLS];   // full-row capacity per warp
    __shared__ int      sh_cnt[WPB];

    // ---- load: 32 elems/thread as 8 float4 (MLP=8, front-batched) ----
    const float4* rp = reinterpret_cast<const float4*>(in + (size_t)row * COLS);
    float4 v[8];
#pragma unroll
    for (int i = 0; i < 8; ++i) v[i] = __ldcs(rp + lane + 32 * i);

    // ---- per-thread max (31 FMNMX tree) ----
    float4 m01 = fmax4(v[0], v[1]), m23 = fmax4(v[2], v[3]);
    float4 m45 = fmax4(v[4], v[5]), m67 = fmax4(v[6], v[7]);
    float4 mm  = fmax4(fmax4(m01, m23), fmax4(m45, m67));
    float lmax = fmaxf(fmaxf(mm.x, mm.y), fmaxf(mm.z, mm.w));

    // ---- t = 6th largest DISTINCT thread-max (ballot-free; t <= v6) ----
    unsigned a = fkey(lmax);
    unsigned kth = 0u;
#pragma unroll
    for (int r = 0; r < TOPK; ++r) {
        unsigned m = redux_max_u32(a);
        kth = m;
        if (a == m) a = 0u;          // ties removed together: distinct-kth
    }
    const float t = funkey(kth);     // identical on all lanes

    // ---- compact candidates (v >= t) into this warp's buffer ----
    if (lane == 0) sh_cnt[warp] = 0;
    __syncwarp();
    if (lmax >= t) {                 // most threads skip the whole scan
#pragma unroll
        for (int i = 0; i < 8; ++i) {
            if (v[i].x >= t) sh_cand[warp][atomicAdd(&sh_cnt[warp],1)] = fkey(v[i].x);
            if (v[i].y >= t) sh_cand[warp][atomicAdd(&sh_cnt[warp],1)] = fkey(v[i].y);
            if (v[i].z >= t) sh_cand[warp][atomicAdd(&sh_cnt[warp],1)] = fkey(v[i].z);
            if (v[i].w >= t) sh_cand[warp][atomicAdd(&sh_cnt[warp],1)] = fkey(v[i].w);
        }
    }
    __syncwarp();

    // ---- lane 0: insertion top-6 (exact) + analytic delta/rinv ----
    float delta, rinv;
    if (lane == 0) {
        const int n = sh_cnt[warp];          // n >= 6 by construction
        unsigned s0=0u,s1=0u,s2=0u,s3=0u,s4=0u,s5=0u;   // s0 >= ... >= s5
        for (int i = 0; i < n; ++i) {
            unsigned x = sh_cand[warp][i];
            if (x > s5) {
                if      (x > s0) { s5=s4;s4=s3;s3=s2;s2=s1;s1=s0;s0=x; }
                else if (x > s1) { s5=s4;s4=s3;s3=s2;s2=s1;s1=x; }
                else if (x > s2) { s5=s4;s4=s3;s3=s2;s2=x; }
                else if (x > s3) { s5=s4;s4=s3;s3=x; }
                else if (x > s4) { s5=s4;s4=x; }
                else             { s5=x; }
            }
        }
        delta = funkey(s5) + EPSV;
        // sum(w) over the whole row == clamped sum over the top-5 only:
        // all other elements are <= v6 < delta -> contribute exactly 0.
        float sum = fmaxf(funkey(s0) - delta, 0.0f)
                  + fmaxf(funkey(s1) - delta, 0.0f)
                  + fmaxf(funkey(s2) - delta, 0.0f)
                  + fmaxf(funkey(s3) - delta, 0.0f)
                  + fmaxf(funkey(s4) - delta, 0.0f);
        rinv = 1.0f / (sum + EPSV);
    }
    delta = __shfl_sync(0xffffffffu, delta, 0);   // broadcast
    rinv  = __shfl_sync(0xffffffffu, rinv,  0);

    // ---- epilogue: clamp * rinv, store (no reduction needed) ----
    float4* op = reinterpret_cast<float4*>(out + (size_t)row * COLS);
#pragma unroll
    for (int i = 0; i < 8; ++i) {
        float4 o4;
        o4.x = fmaxf(v[i].x - delta, 0.0f) * rinv;
        o4.y = fmaxf(v[i].y - delta, 0.0f) * rinv;
        o4.z = fmaxf(v[i].z - delta, 0.0f) * rinv;
        o4.w = fmaxf(v[i].w - delta, 0.0f) * rinv;
        __stcs(op + lane + 32 * i, o4);
    }
}

extern "C" void kernel_launch(void* const* d_in, const int* in_sizes, int n_in,
                              void* d_out, int out_size) {
    const float* in = (const float*)d_in[0];
    float* out = (float*)d_out;
    const int rows = in_sizes[0] / COLS;           // 65536 for reference shape
    const int grid = (rows + WPB - 1) / WPB;
    topk_renorm_kernel<<<grid, 32 * WPB>>>(in, out, rows);
}